// round 6
// baseline (speedup 1.0000x reference)
#include <cuda_runtime.h>
#include <cuda_pipeline.h>

// BiLinearInteractionLayer: out[b, p, :] = (x[b,i_p,:] @ W) * x[b,j_p,:]
// x: [2048, 40, 64] fp32, W: [64, 64] fp32, out: [2048, 780*64] fp32.
//
// PERSISTENT version: 740 CTAs (148 SM x 5), each loops over batches with
// stride 740. W staged in smem once per CTA. x double-buffered with cp.async
// so the next batch's load overlaps the current batch's GEMM + stores.
// Goal: keep the DRAM write stream continuous (no wave boundaries, no
// exposed phase-1 latency) — measured when-active DRAM BW is ~spec, the
// loss is idle gaps.
//
// Per-batch compute = R3 structure: thread (col = tid&15, fb = tid>>4) keeps
// xw rows {fb, 31-fb, 32+fb} in registers, then streams pair products with
// one LDS.128 per STG.128.

#define F_NUM   40
#define EDIM    64
#define RPAD    68          // floats per sx row: bank stride 4 mod 32
#define RPAD4   17
#define NPAIR   780
#define TPB     256
#define GRID    740         // 148 SMs x 5 resident CTAs
#define BATCH_N 2048

__global__ __launch_bounds__(TPB, 5)
void bilinear_interact_kernel(const float* __restrict__ x,
                              const float* __restrict__ w,
                              float* __restrict__ out)
{
    __shared__ float sx[2][F_NUM * RPAD];  // 2 x 10.6 KB
    __shared__ float sw[EDIM * EDIM];      // 16 KB

    const int tid = threadIdx.x;
    const int b0  = blockIdx.x;

    // ---- One-time: stage W ------------------------------------------------
    {
        const float4* wg  = reinterpret_cast<const float4*>(w);
        float4*       sw4 = reinterpret_cast<float4*>(sw);
        #pragma unroll
        for (int t = tid; t < EDIM * EDIM / 4; t += TPB) sw4[t] = wg[t];
    }

    // ---- Prefetch first batch into buffer 0 --------------------------------
    {
        const float* xg = x + (size_t)b0 * F_NUM * EDIM;
        #pragma unroll
        for (int t = tid; t < F_NUM * EDIM / 4; t += TPB) {
            const int row = t >> 4;
            const int c   = t & 15;
            __pipeline_memcpy_async(&sx[0][row * RPAD + c * 4], xg + t * 4, 16);
        }
        __pipeline_commit();
    }

    const int col = tid & 15;                    // float4 column (d/4)
    const int fb  = tid >> 4;                    // 0..15
    const int i0  = fb;                          // 0..15
    const int i1  = 31 - fb;                     // 16..31
    const int i2  = (fb < 8) ? (32 + fb) : 39;   // 32..39 (fb>=8: row 39, nj=0)

    int cur = 0;
    for (int b = b0; b < BATCH_N; b += GRID, cur ^= 1) {
        // ---- Prefetch next batch into the other buffer ---------------------
        const int bn = b + GRID;
        if (bn < BATCH_N) {
            const float* xg = x + (size_t)bn * F_NUM * EDIM;
            #pragma unroll
            for (int t = tid; t < F_NUM * EDIM / 4; t += TPB) {
                const int row = t >> 4;
                const int c   = t & 15;
                __pipeline_memcpy_async(&sx[cur ^ 1][row * RPAD + c * 4], xg + t * 4, 16);
            }
            __pipeline_commit();
            __pipeline_wait_prior(1);   // current buffer's group done
        } else {
            __pipeline_wait_prior(0);
        }
        __syncthreads();                // sx[cur] visible to all threads

        const float* sxc = sx[cur];

        // ---- Phase 2: xw rows {i0,i1,i2} -> registers ----------------------
        float4 acc0 = make_float4(0.f, 0.f, 0.f, 0.f);
        float4 acc1 = acc0;
        float4 acc2 = acc0;
        {
            const float4* swv = reinterpret_cast<const float4*>(sw);
            #pragma unroll 8
            for (int k = 0; k < EDIM; k++) {
                const float4 wv = swv[k * 16 + col];
                const float a0 = sxc[i0 * RPAD + k];
                const float a1 = sxc[i1 * RPAD + k];
                const float a2 = sxc[i2 * RPAD + k];
                acc0.x += a0 * wv.x; acc0.y += a0 * wv.y; acc0.z += a0 * wv.z; acc0.w += a0 * wv.w;
                acc1.x += a1 * wv.x; acc1.y += a1 * wv.y; acc1.z += a1 * wv.z; acc1.w += a1 * wv.w;
                acc2.x += a2 * wv.x; acc2.y += a2 * wv.y; acc2.z += a2 * wv.z; acc2.w += a2 * wv.w;
            }
        }

        // ---- Phase 3: stream pair products from registers ------------------
        {
            float4*       out4 = reinterpret_cast<float4*>(out + (size_t)b * NPAIR * EDIM);
            const float4* sx4  = reinterpret_cast<const float4*>(sxc);

            #pragma unroll
            for (int r = 0; r < 3; r++) {
                const int    i  = (r == 0) ? i0 : (r == 1) ? i1 : i2;
                const float4 a  = (r == 0) ? acc0 : (r == 1) ? acc1 : acc2;
                const int    nj = F_NUM - 1 - i;
                const int    pb = (i * (2 * F_NUM - 1 - i)) >> 1;   // i*(79-i)/2
                float4*       ob = out4 + (size_t)pb * 16 + col;
                const float4* vb = sx4 + (size_t)(i + 1) * RPAD4 + col;
                #pragma unroll 4
                for (int jo = 0; jo < nj; jo++) {
                    const float4 v = vb[jo * RPAD4];
                    const float4 p = make_float4(a.x * v.x, a.y * v.y,
                                                 a.z * v.z, a.w * v.w);
                    __stcs(ob + jo * 16, p);
                }
            }
        }

        __syncthreads();   // all phase-3 reads of sx[cur] done before next
                           // iteration's prefetch overwrites it
    }
}

extern "C" void kernel_launch(void* const* d_in, const int* in_sizes, int n_in,
                              void* d_out, int out_size)
{
    const float* x = (const float*)d_in[0];   // [2048, 40, 64]
    const float* w = (const float*)d_in[1];   // [64, 64]
    float* out = (float*)d_out;               // [2048, 780*64]
    (void)in_sizes; (void)n_in; (void)out_size;

    bilinear_interact_kernel<<<GRID, TPB>>>(x, w, out);
}

// round 7
// speedup vs baseline: 1.0593x; 1.0593x over previous
#include <cuda_runtime.h>

// BiLinearInteractionLayer: out[b, p, :] = (x[b,i_p,:] @ W) * x[b,j_p,:]
// x: [2048, 40, 64] fp32, W: [64, 64] fp32, out: [2048, 780*64] fp32.
//
// One CTA per batch row (best-measured structure, R3 base).
// Thread (col = tid&15, fb = tid>>4) keeps xw rows {fb, 31-fb, 32+fb} in
// registers (no sxw smem), then streams pair products with exactly one
// LDS.128 per STG.128.
// R7 deltas: 6 CTAs/SM (42-reg cap), and warps 4-7 (fb>=8, warp-uniform)
// skip the dead third row (row 39 is never a left operand).

#define F_NUM   40
#define EDIM    64
#define RPAD    68          // floats per sx row -> bank stride 4 mod 32
#define RPAD4   17
#define NPAIR   780
#define TPB     256
#define BATCH_N 2048

__global__ __launch_bounds__(TPB, 6)
void bilinear_interact_kernel(const float* __restrict__ x,
                              const float* __restrict__ w,
                              float* __restrict__ out)
{
    __shared__ float sx[F_NUM * RPAD];    // 10.6 KB
    __shared__ float sw[EDIM * EDIM];     // 16 KB

    const int b   = blockIdx.x;
    const int tid = threadIdx.x;

    // ---- Phase 1: stage inputs ------------------------------------------
    {
        const float4* xg  = reinterpret_cast<const float4*>(x + (size_t)b * F_NUM * EDIM);
        float4*       sx4 = reinterpret_cast<float4*>(sx);
        #pragma unroll
        for (int t = tid; t < F_NUM * EDIM / 4; t += TPB) {
            const int row = t >> 4;
            const int c   = t & 15;
            sx4[row * RPAD4 + c] = xg[t];
        }
        const float4* wg  = reinterpret_cast<const float4*>(w);
        float4*       sw4 = reinterpret_cast<float4*>(sw);
        #pragma unroll
        for (int t = tid; t < EDIM * EDIM / 4; t += TPB) sw4[t] = wg[t];
    }
    __syncthreads();

    const int col = tid & 15;   // float4 column (d/4)
    const int fb  = tid >> 4;   // 0..15

    const int i0 = fb;          // 0..15
    const int i1 = 31 - fb;     // 16..31
    const int i2 = 32 + fb;     // 32..39, only live for fb < 8

    // ---- Phase 2: xw rows -> registers ----------------------------------
    float4 acc0 = make_float4(0.f, 0.f, 0.f, 0.f);
    float4 acc1 = acc0;
    float4 acc2 = acc0;
    {
        const float4* swv = reinterpret_cast<const float4*>(sw);
        if (fb < 8) {           // warp-uniform: warps 0-3 take this branch
            #pragma unroll 8
            for (int k = 0; k < EDIM; k++) {
                const float4 wv = swv[k * 16 + col];
                const float a0 = sx[i0 * RPAD + k];
                const float a1 = sx[i1 * RPAD + k];
                const float a2 = sx[i2 * RPAD + k];
                acc0.x += a0 * wv.x; acc0.y += a0 * wv.y; acc0.z += a0 * wv.z; acc0.w += a0 * wv.w;
                acc1.x += a1 * wv.x; acc1.y += a1 * wv.y; acc1.z += a1 * wv.z; acc1.w += a1 * wv.w;
                acc2.x += a2 * wv.x; acc2.y += a2 * wv.y; acc2.z += a2 * wv.z; acc2.w += a2 * wv.w;
            }
        } else {                // warps 4-7: only 2 live rows
            #pragma unroll 8
            for (int k = 0; k < EDIM; k++) {
                const float4 wv = swv[k * 16 + col];
                const float a0 = sx[i0 * RPAD + k];
                const float a1 = sx[i1 * RPAD + k];
                acc0.x += a0 * wv.x; acc0.y += a0 * wv.y; acc0.z += a0 * wv.z; acc0.w += a0 * wv.w;
                acc1.x += a1 * wv.x; acc1.y += a1 * wv.y; acc1.z += a1 * wv.z; acc1.w += a1 * wv.w;
            }
        }
    }
    // No sync: phase 3 reads sx (already sync'd) and registers only.

    // ---- Phase 3: stream pair products from registers --------------------
    // pb(i) = i*(79-i)/2 ; out[b, pb(i)+jo, :] = xw[i] * x[i+1+jo]
    {
        float4*       out4 = reinterpret_cast<float4*>(out + (size_t)b * NPAIR * EDIM);
        const float4* sx4  = reinterpret_cast<const float4*>(sx);

        // row i0
        {
            const int nj = F_NUM - 1 - i0;
            const int pb = (i0 * (2 * F_NUM - 1 - i0)) >> 1;
            float4*       ob = out4 + (size_t)pb * 16 + col;
            const float4* vb = sx4 + (size_t)(i0 + 1) * RPAD4 + col;
            #pragma unroll 4
            for (int jo = 0; jo < nj; jo++) {
                const float4 v = vb[jo * RPAD4];
                __stcs(ob + jo * 16, make_float4(acc0.x * v.x, acc0.y * v.y,
                                                 acc0.z * v.z, acc0.w * v.w));
            }
        }
        // row i1
        {
            const int nj = F_NUM - 1 - i1;
            const int pb = (i1 * (2 * F_NUM - 1 - i1)) >> 1;
            float4*       ob = out4 + (size_t)pb * 16 + col;
            const float4* vb = sx4 + (size_t)(i1 + 1) * RPAD4 + col;
            #pragma unroll 4
            for (int jo = 0; jo < nj; jo++) {
                const float4 v = vb[jo * RPAD4];
                __stcs(ob + jo * 16, make_float4(acc1.x * v.x, acc1.y * v.y,
                                                 acc1.z * v.z, acc1.w * v.w));
            }
        }
        // row i2 (warps 0-3 only; warp-uniform branch)
        if (fb < 8) {
            const int nj = F_NUM - 1 - i2;
            const int pb = (i2 * (2 * F_NUM - 1 - i2)) >> 1;
            float4*       ob = out4 + (size_t)pb * 16 + col;
            const float4* vb = sx4 + (size_t)(i2 + 1) * RPAD4 + col;
            #pragma unroll 4
            for (int jo = 0; jo < nj; jo++) {
                const float4 v = vb[jo * RPAD4];
                __stcs(ob + jo * 16, make_float4(acc2.x * v.x, acc2.y * v.y,
                                                 acc2.z * v.z, acc2.w * v.w));
            }
        }
    }
}

extern "C" void kernel_launch(void* const* d_in, const int* in_sizes, int n_in,
                              void* d_out, int out_size)
{
    const float* x = (const float*)d_in[0];   // [2048, 40, 64]
    const float* w = (const float*)d_in[1];   // [64, 64]
    float* out = (float*)d_out;               // [2048, 780*64]
    (void)in_sizes; (void)n_in; (void)out_size;

    bilinear_interact_kernel<<<BATCH_N, TPB>>>(x, w, out);
}